// round 3
// baseline (speedup 1.0000x reference)
#include <cuda_runtime.h>
#include <math.h>

#define FS        100.0f
#define N_FILT    12
#define N_CH      27
#define FILT_DIM  5
#define BATCH     8
#define T_IN      65536
#define T_OUT     (T_IN - FILT_DIM + 1)   // 65532
#define NVEC      (T_OUT / 4)             // 16383 float4 outputs per row
#define TWO_PI    6.283185307179586f

// ---------------------------------------------------------------------------
// Fused kernel: threads 0..11 build this channel's 12 sinc filters in smem,
// then every thread produces 2 float4 outputs (8 samples) for all 12 filters.
// Grid: (ceil(NVEC/512), N_CH, BATCH), block 256.
// ---------------------------------------------------------------------------
__global__ __launch_bounds__(256)
void sinc_conv_fused_kernel(const float* __restrict__ x,
                            const float* __restrict__ filt_low,
                            const float* __restrict__ filt_band,
                            float* __restrict__ out)
{
    const int c = blockIdx.y;
    const int b = blockIdx.z;

    __shared__ float sf[N_FILT * FILT_DIM];   // 60 taps for this channel

    if (threadIdx.x < N_FILT) {
        const int f   = threadIdx.x;
        const int idx = c * N_FILT + f;

        float beg = fabsf(filt_low[idx]) + (1.0f / FS);
        float end = beg + fabsf(filt_band[idx]);

        // low_pass(freq) taps: 2*freq * [y1, y0, 1, y0, y1]
        // arg_k = 2*pi*FS*freq*t_k,  t = {1,2}/FS
        float ae0 = TWO_PI * FS * end * (1.0f / FS);
        float ae1 = TWO_PI * FS * end * (2.0f / FS);
        float ab0 = TWO_PI * FS * beg * (1.0f / FS);
        float ab1 = TWO_PI * FS * beg * (2.0f / FS);
        float ye0 = sinf(ae0) / ae0;
        float ye1 = sinf(ae1) / ae1;
        float yb0 = sinf(ab0) / ab0;
        float yb1 = sinf(ab1) / ab1;
        float se = 2.0f * end, sb = 2.0f * beg;

        float bp0 = se * ye1 - sb * yb1;   // taps 0 and 4
        float bp1 = se * ye0 - sb * yb0;   // taps 1 and 3
        float bp2 = se       - sb;         // tap 2

        float mx = fmaxf(bp2, fmaxf(bp1, bp0));

        // window at n = k*1.25:  0.42 - 0.5*cos(2*pi*n/5) + 0.08*cos(4*pi*n/5)
        #pragma unroll
        for (int k = 0; k < FILT_DIM; k++) {
            float n = (float)k * 1.25f;
            float w = 0.42f - 0.5f * cosf(TWO_PI * n * 0.2f)
                            + 0.08f * cosf(2.0f * TWO_PI * n * 0.2f);
            float bp = (k == 2) ? bp2 : ((k == 1 || k == 3) ? bp1 : bp0);
            sf[f * FILT_DIM + k] = (bp / mx) * w;
        }
    }
    __syncthreads();

    const int p  = blockIdx.x * blockDim.x + threadIdx.x;  // pair index
    const int i0 = p * 2;                                   // first float4 pos
    if (i0 >= NVEC) return;
    const bool full = (i0 + 1 < NVEC);

    const float4* x4 = (const float4*)(x + ((size_t)b * N_CH + c) * T_IN);
    float4 v0 = x4[i0];
    float4 v1 = x4[i0 + 1];                 // always in bounds (<= 16383)
    float4 v2;
    if (full) v2 = x4[i0 + 2];
    else      v2 = make_float4(0.f, 0.f, 0.f, 0.f);

    float* orow = out + (((size_t)b * N_CH + c) * N_FILT) * T_OUT + (size_t)i0 * 4;

    #pragma unroll
    for (int f = 0; f < N_FILT; f++) {
        const float w0 = sf[f * FILT_DIM + 0];
        const float w1 = sf[f * FILT_DIM + 1];
        const float w2 = sf[f * FILT_DIM + 2];
        const float w3 = sf[f * FILT_DIM + 3];
        const float w4 = sf[f * FILT_DIM + 4];

        float4 r0, r1;
        r0.x = w0*v0.x + w1*v0.y + w2*v0.z + w3*v0.w + w4*v1.x;
        r0.y = w0*v0.y + w1*v0.z + w2*v0.w + w3*v1.x + w4*v1.y;
        r0.z = w0*v0.z + w1*v0.w + w2*v1.x + w3*v1.y + w4*v1.z;
        r0.w = w0*v0.w + w1*v1.x + w2*v1.y + w3*v1.z + w4*v1.w;

        r1.x = w0*v1.x + w1*v1.y + w2*v1.z + w3*v1.w + w4*v2.x;
        r1.y = w0*v1.y + w1*v1.z + w2*v1.w + w3*v2.x + w4*v2.y;
        r1.z = w0*v1.z + w1*v1.w + w2*v2.x + w3*v2.y + w4*v2.z;
        r1.w = w0*v1.w + w1*v2.x + w2*v2.y + w3*v2.z + w4*v2.w;

        float4* op = (float4*)(orow + (size_t)f * T_OUT);
        __stcs(op, r0);
        if (full) __stcs(op + 1, r1);
    }
}

extern "C" void kernel_launch(void* const* d_in, const int* in_sizes, int n_in,
                              void* d_out, int out_size)
{
    const float* x         = (const float*)d_in[0];
    const float* filt_low  = (const float*)d_in[1];
    const float* filt_band = (const float*)d_in[2];
    float* out             = (float*)d_out;

    const int pairs = (NVEC + 1) / 2;                    // 8192
    dim3 grid((pairs + 255) / 256, N_CH, BATCH);         // 32 x 27 x 8
    sinc_conv_fused_kernel<<<grid, 256>>>(x, filt_low, filt_band, out);
}

// round 5
// speedup vs baseline: 1.5319x; 1.5319x over previous
#include <cuda_runtime.h>
#include <math.h>

#define FS        100.0f
#define N_FILT    12
#define N_CH      27
#define FILT_DIM  5
#define BATCH     8
#define T_IN      65536
#define T_OUT     (T_IN - FILT_DIM + 1)   // 65532
#define NVEC      (T_OUT / 4)             // 16383 float4 outputs per row
#define TWO_PI    6.283185307179586f

// ---------------------------------------------------------------------------
// Fused: threads 0..11 build this channel's 12 sinc filters into smem, then
// every thread produces 1 float4 (4 samples) for all 12 filters.
// Warp store pattern: 32 lanes x contiguous float4 = 512 B contiguous per row.
// Grid: (ceil(NVEC/256), N_CH, BATCH), block 256.
// ---------------------------------------------------------------------------
__global__ __launch_bounds__(256)
void sinc_conv_fused_kernel(const float* __restrict__ x,
                            const float* __restrict__ filt_low,
                            const float* __restrict__ filt_band,
                            float* __restrict__ out)
{
    const int c = blockIdx.y;
    const int b = blockIdx.z;

    __shared__ float sf[N_FILT * FILT_DIM];   // 60 taps for this channel

    if (threadIdx.x < N_FILT) {
        const int f   = threadIdx.x;
        const int idx = c * N_FILT + f;

        float beg = fabsf(filt_low[idx]) + (1.0f / FS);
        float end = beg + fabsf(filt_band[idx]);

        // low_pass(freq) taps: 2*freq * [y1, y0, 1, y0, y1]
        // arg_k = 2*pi*FS*freq*t_k, t = {1,2}/FS
        float ae0 = TWO_PI * FS * end * (1.0f / FS);
        float ae1 = TWO_PI * FS * end * (2.0f / FS);
        float ab0 = TWO_PI * FS * beg * (1.0f / FS);
        float ab1 = TWO_PI * FS * beg * (2.0f / FS);
        float ye0 = sinf(ae0) / ae0;
        float ye1 = sinf(ae1) / ae1;
        float yb0 = sinf(ab0) / ab0;
        float yb1 = sinf(ab1) / ab1;
        float se = 2.0f * end, sb = 2.0f * beg;

        float bp0 = se * ye1 - sb * yb1;   // taps 0 and 4
        float bp1 = se * ye0 - sb * yb0;   // taps 1 and 3
        float bp2 = se       - sb;         // tap 2

        float mx = fmaxf(bp2, fmaxf(bp1, bp0));

        // window at n = k*1.25: 0.42 - 0.5*cos(2*pi*n/5) + 0.08*cos(4*pi*n/5)
        #pragma unroll
        for (int k = 0; k < FILT_DIM; k++) {
            float n = (float)k * 1.25f;
            float w = 0.42f - 0.5f * cosf(TWO_PI * n * 0.2f)
                            + 0.08f * cosf(2.0f * TWO_PI * n * 0.2f);
            float bp = (k == 2) ? bp2 : ((k == 1 || k == 3) ? bp1 : bp0);
            sf[f * FILT_DIM + k] = (bp / mx) * w;
        }
    }
    __syncthreads();

    const int i = blockIdx.x * blockDim.x + threadIdx.x;   // float4 position
    if (i >= NVEC) return;

    const float4* x4 = (const float4*)(x + ((size_t)b * N_CH + c) * T_IN);
    float4 v0 = x4[i];
    float4 v1 = x4[i + 1];   // i <= 16382 -> i+1 <= 16383 (covers x[65532..65535])

    float* orow = out + (((size_t)b * N_CH + c) * N_FILT) * T_OUT + (size_t)i * 4;

    #pragma unroll
    for (int f = 0; f < N_FILT; f++) {
        const float w0 = sf[f * FILT_DIM + 0];
        const float w1 = sf[f * FILT_DIM + 1];
        const float w2 = sf[f * FILT_DIM + 2];
        const float w3 = sf[f * FILT_DIM + 3];
        const float w4 = sf[f * FILT_DIM + 4];

        float4 r;
        r.x = w0*v0.x + w1*v0.y + w2*v0.z + w3*v0.w + w4*v1.x;
        r.y = w0*v0.y + w1*v0.z + w2*v0.w + w3*v1.x + w4*v1.y;
        r.z = w0*v0.z + w1*v0.w + w2*v1.x + w3*v1.y + w4*v1.z;
        r.w = w0*v0.w + w1*v1.x + w2*v1.y + w3*v1.z + w4*v1.w;

        *(float4*)(orow + (size_t)f * T_OUT) = r;
    }
}

extern "C" void kernel_launch(void* const* d_in, const int* in_sizes, int n_in,
                              void* d_out, int out_size)
{
    const float* x         = (const float*)d_in[0];
    const float* filt_low  = (const float*)d_in[1];
    const float* filt_band = (const float*)d_in[2];
    float* out             = (float*)d_out;

    dim3 grid((NVEC + 255) / 256, N_CH, BATCH);   // 64 x 27 x 8
    sinc_conv_fused_kernel<<<grid, 256>>>(x, filt_low, filt_band, out);
}